// round 9
// baseline (speedup 1.0000x reference)
#include <cuda_runtime.h>
#include <cuda_bf16.h>

// Problem constants (fixed by the reference)
#define BATCH 4
#define NCH 3
#define NCLS 20
#define HH 512
#define WW 512
#define MAXB 50
#define NSLICE 16
#define ROWG 8                         // row-groups per block (ty)
#define LANES 32                       // lanes per row-group (x, each handles float4)
#define ROWSTRIDE (NSLICE * ROWG)      // 128-way row interleave per box
#define NJOBS (BATCH * MAXB * NSLICE)  // 3200 jobs; job j -> partial slot j
#define NBLOCKS 592

// Scratch (no allocation): deterministic partial slots + int counters
__device__ float g_partials[NJOBS];
__device__ int   g_ticket  = 0;        // work-stealing ticket
__device__ int   g_counter = 0;        // finished-blocks counter (last-block finalize)

// Scalar accumulation over [xa, xb) of one row (3 channels), lanes strided by LANES.
__device__ __forceinline__ float row_scalar(
    const float* __restrict__ ir0, const float* __restrict__ ir1, const float* __restrict__ ir2,
    const float* __restrict__ yr0, const float* __restrict__ yr1, const float* __restrict__ yr2,
    int xa, int xb, int tx, float acc)
{
    for (int x = xa + tx; x < xb; x += LANES) {
        float d0 = ir0[x] - yr0[x];
        float d1 = ir1[x] - yr1[x];
        float d2 = ir2[x] - yr2[x];
        acc = fmaf(d0, d0, acc);
        acc = fmaf(d1, d1, acc);
        acc = fmaf(d2, d2, acc);
    }
    return acc;
}

// Vector accumulation over aligned [vx1, vx2) of one row (3 channels).
__device__ __forceinline__ float row_vector(
    const float* __restrict__ ir0, const float* __restrict__ ir1, const float* __restrict__ ir2,
    const float* __restrict__ yr0, const float* __restrict__ yr1, const float* __restrict__ yr2,
    int vx1, int vx2, int tx, float acc)
{
    for (int x = vx1 + tx * 4; x < vx2; x += LANES * 4) {
        float4 a0 = *(const float4*)(ir0 + x);
        float4 c0 = *(const float4*)(yr0 + x);
        float4 a1 = *(const float4*)(ir1 + x);
        float4 c1 = *(const float4*)(yr1 + x);
        float4 a2 = *(const float4*)(ir2 + x);
        float4 c2 = *(const float4*)(yr2 + x);
        float d;
        d = a0.x - c0.x; acc = fmaf(d, d, acc);
        d = a0.y - c0.y; acc = fmaf(d, d, acc);
        d = a0.z - c0.z; acc = fmaf(d, d, acc);
        d = a0.w - c0.w; acc = fmaf(d, d, acc);
        d = a1.x - c1.x; acc = fmaf(d, d, acc);
        d = a1.y - c1.y; acc = fmaf(d, d, acc);
        d = a1.z - c1.z; acc = fmaf(d, d, acc);
        d = a1.w - c1.w; acc = fmaf(d, d, acc);
        d = a2.x - c2.x; acc = fmaf(d, d, acc);
        d = a2.y - c2.y; acc = fmaf(d, d, acc);
        d = a2.z - c2.z; acc = fmaf(d, d, acc);
        d = a2.w - c2.w; acc = fmaf(d, d, acc);
    }
    return acc;
}

__global__ void __launch_bounds__(256) box_sum_kernel(
    const float* __restrict__ y_fcn,    // [B, NCLS*NCH, H, W]
    const float* __restrict__ im_data,  // [B, NCH, H, W]
    const int*   __restrict__ gt_boxes, // [B, MAXB, 5] (x1,y1,x2,y2,cls)
    const int*   __restrict__ num_boxes,// [B]
    float*       __restrict__ out
) {
    const int tid  = threadIdx.x;
    const int lane = tid & 31;
    const int wid  = tid >> 5;
    const int tx   = tid & (LANES - 1);     // 0..31
    const int ty   = tid / LANES;           // 0..7

    __shared__ int   job_s;
    __shared__ float warp_sums[8];

    const size_t plane = (size_t)HH * WW;

    for (;;) {
        __syncthreads();                     // protect job_s / warp_sums reuse
        if (tid == 0) job_s = atomicAdd(&g_ticket, 1);
        __syncthreads();
        const int j = job_s;
        if (j >= NJOBS) break;

        const int bb    = j / NSLICE;        // 0 .. B*MAXB-1
        const int slice = j % NSLICE;        // 0 .. NSLICE-1
        const int b     = bb / MAXB;
        const int box   = bb % MAXB;

        if (box >= __ldg(&num_boxes[b])) {   // empty job: write slot, next ticket
            if (tid == 0) g_partials[j] = 0.0f;
            continue;
        }

        const int* g  = gt_boxes + bb * 5;
        const int x1  = __ldg(&g[0]);
        const int y1  = __ldg(&g[1]);
        const int x2  = __ldg(&g[2]);
        const int y2  = __ldg(&g[3]);
        const int cls = __ldg(&g[4]);

        // class cls occupies channels [cls*NCH, (cls+1)*NCH) of y_fcn
        const float* yb = y_fcn   + ((size_t)b * (NCLS * NCH) + (size_t)cls * NCH) * plane;
        const float* ib = im_data + (size_t)b * NCH * plane;

        const int vx1 = (x1 + 3) & ~3;       // aligned interior for float4
        const int vx2 = x2 & ~3;
        const int rowWorker = slice * ROWG + ty;   // 0..127

        float accA = 0.0f;                   // row-pair accumulator A (row r)
        float accB = 0.0f;                   // row-pair accumulator B (row r+ROWSTRIDE)

        int r = y1 + rowWorker;

        if (vx1 < vx2) {
            // ---- dual-row pairs: 12 independent LDG.128 per body -> 2x MLP ----
            for (; r + ROWSTRIDE < y2; r += 2 * ROWSTRIDE) {
                const size_t ro = (size_t)r * WW;
                const size_t so = ro + (size_t)ROWSTRIDE * WW;
                const float* yr0 = yb + ro;  const float* ys0 = yb + so;
                const float* yr1 = yr0 + plane; const float* ys1 = ys0 + plane;
                const float* yr2 = yr1 + plane; const float* ys2 = ys1 + plane;
                const float* ir0 = ib + ro;  const float* is0 = ib + so;
                const float* ir1 = ir0 + plane; const float* is1 = is0 + plane;
                const float* ir2 = ir1 + plane; const float* is2 = is1 + plane;

                // head scalar for both rows
                accA = row_scalar(ir0, ir1, ir2, yr0, yr1, yr2, x1, vx1, tx, accA);
                accB = row_scalar(is0, is1, is2, ys0, ys1, ys2, x1, vx1, tx, accB);

                // fused dual-row vector body
                for (int x = vx1 + tx * 4; x < vx2; x += LANES * 4) {
                    float4 a0 = *(const float4*)(ir0 + x);
                    float4 a1 = *(const float4*)(ir1 + x);
                    float4 a2 = *(const float4*)(ir2 + x);
                    float4 e0 = *(const float4*)(is0 + x);
                    float4 e1 = *(const float4*)(is1 + x);
                    float4 e2 = *(const float4*)(is2 + x);
                    float4 c0 = *(const float4*)(yr0 + x);
                    float4 c1 = *(const float4*)(yr1 + x);
                    float4 c2 = *(const float4*)(yr2 + x);
                    float4 f0 = *(const float4*)(ys0 + x);
                    float4 f1 = *(const float4*)(ys1 + x);
                    float4 f2 = *(const float4*)(ys2 + x);
                    float d;
                    d = a0.x - c0.x; accA = fmaf(d, d, accA);
                    d = a0.y - c0.y; accA = fmaf(d, d, accA);
                    d = a0.z - c0.z; accA = fmaf(d, d, accA);
                    d = a0.w - c0.w; accA = fmaf(d, d, accA);
                    d = e0.x - f0.x; accB = fmaf(d, d, accB);
                    d = e0.y - f0.y; accB = fmaf(d, d, accB);
                    d = e0.z - f0.z; accB = fmaf(d, d, accB);
                    d = e0.w - f0.w; accB = fmaf(d, d, accB);
                    d = a1.x - c1.x; accA = fmaf(d, d, accA);
                    d = a1.y - c1.y; accA = fmaf(d, d, accA);
                    d = a1.z - c1.z; accA = fmaf(d, d, accA);
                    d = a1.w - c1.w; accA = fmaf(d, d, accA);
                    d = e1.x - f1.x; accB = fmaf(d, d, accB);
                    d = e1.y - f1.y; accB = fmaf(d, d, accB);
                    d = e1.z - f1.z; accB = fmaf(d, d, accB);
                    d = e1.w - f1.w; accB = fmaf(d, d, accB);
                    d = a2.x - c2.x; accA = fmaf(d, d, accA);
                    d = a2.y - c2.y; accA = fmaf(d, d, accA);
                    d = a2.z - c2.z; accA = fmaf(d, d, accA);
                    d = a2.w - c2.w; accA = fmaf(d, d, accA);
                    d = e2.x - f2.x; accB = fmaf(d, d, accB);
                    d = e2.y - f2.y; accB = fmaf(d, d, accB);
                    d = e2.z - f2.z; accB = fmaf(d, d, accB);
                    d = e2.w - f2.w; accB = fmaf(d, d, accB);
                }

                // tail scalar for both rows
                accA = row_scalar(ir0, ir1, ir2, yr0, yr1, yr2, vx2, x2, tx, accA);
                accB = row_scalar(is0, is1, is2, ys0, ys1, ys2, vx2, x2, tx, accB);
            }
            // leftover single row
            if (r < y2) {
                const size_t ro = (size_t)r * WW;
                const float* yr0 = yb + ro;
                const float* yr1 = yr0 + plane;
                const float* yr2 = yr1 + plane;
                const float* ir0 = ib + ro;
                const float* ir1 = ir0 + plane;
                const float* ir2 = ir1 + plane;
                accA = row_scalar(ir0, ir1, ir2, yr0, yr1, yr2, x1, vx1, tx, accA);
                accA = row_vector(ir0, ir1, ir2, yr0, yr1, yr2, vx1, vx2, tx, accA);
                accA = row_scalar(ir0, ir1, ir2, yr0, yr1, yr2, vx2, x2, tx, accA);
            }
        } else {
            // narrow box (< 4 aligned cols): all scalar, row at a time
            for (; r < y2; r += ROWSTRIDE) {
                const size_t ro = (size_t)r * WW;
                const float* yr0 = yb + ro;
                const float* yr1 = yr0 + plane;
                const float* yr2 = yr1 + plane;
                const float* ir0 = ib + ro;
                const float* ir1 = ir0 + plane;
                const float* ir2 = ir1 + plane;
                accA = row_scalar(ir0, ir1, ir2, yr0, yr1, yr2, x1, x2, tx, accA);
            }
        }

        float acc = accA + accB;
        const int area = (y2 - y1) * (x2 - x1);
        acc *= 1.0f / (float)(NCH * (area > 1 ? area : 1));  // linear -> same as scaling sum

        // Deterministic block reduction into slot j
        #pragma unroll
        for (int off = 16; off > 0; off >>= 1)
            acc += __shfl_down_sync(0xFFFFFFFFu, acc, off);
        if (lane == 0) warp_sums[wid] = acc;
        __syncthreads();
        if (wid == 0) {
            float s = (lane < 8) ? warp_sums[lane] : 0.0f;
            #pragma unroll
            for (int off = 4; off > 0; off >>= 1)
                s += __shfl_down_sync(0xFFFFFFFFu, s, off);
            if (lane == 0) g_partials[j] = s;
        }
    }

    // ---- last-block-done fused finalize ----
    __shared__ bool is_last;
    if (tid == 0) {
        __threadfence();                       // publish our partials
        int prev = atomicAdd(&g_counter, 1);
        is_last = (prev == NBLOCKS - 1);
    }
    __syncthreads();

    if (is_last) {
        __threadfence();                       // see everyone's partials

        float s = 0.0f;
        #pragma unroll 4
        for (int i = tid; i < NJOBS; i += 256)
            s += g_partials[i];                // fixed order -> deterministic

        #pragma unroll
        for (int off = 16; off > 0; off >>= 1)
            s += __shfl_down_sync(0xFFFFFFFFu, s, off);

        __shared__ float fin_sums[8];
        if (lane == 0) fin_sums[wid] = s;
        __syncthreads();

        if (wid == 0) {
            float t = (lane < 8) ? fin_sums[lane] : 0.0f;
            #pragma unroll
            for (int off = 4; off > 0; off >>= 1)
                t += __shfl_down_sync(0xFFFFFFFFu, t, off);
            if (lane == 0) {
                int nb = num_boxes[0] + num_boxes[1] + num_boxes[2] + num_boxes[3];
                out[0] = t / (float)nb;
                g_ticket  = 0;                 // reset for next graph replay
                g_counter = 0;
            }
        }
    }
}

extern "C" void kernel_launch(void* const* d_in, const int* in_sizes, int n_in,
                              void* d_out, int out_size) {
    const float* y_fcn     = (const float*)d_in[0];
    const float* im_data   = (const float*)d_in[1];
    // d_in[2] = im_info (unused)
    const int*   gt_boxes  = (const int*)d_in[3];
    const int*   num_boxes = (const int*)d_in[4];
    float*       out       = (float*)d_out;

    box_sum_kernel<<<NBLOCKS, 256>>>(y_fcn, im_data, gt_boxes, num_boxes, out);
}